// round 3
// baseline (speedup 1.0000x reference)
#include <cuda_runtime.h>
#include <math.h>

// hidden_states: [16, 13, 512, 768] fp32, reduce over axis=2 (512)
// out: [16, 13, 2304] = concat(sum, std(ddof=1), max) along last axis.
//
// R3: float4 (LDG.128) columns. One thread per 4 consecutive h:
// 208 * 192 = 39936 threads. Warp request = 512 B contiguous
// (4x fewer L2/DRAM transactions, 4x bytes-in-flight per load slot).

#define BL    208      // 16 * 13
#define SEQ   512
#define HID   768
#define H4    (HID / 4)   // 192 float4 per row
#define TPB   64

__global__ void __launch_bounds__(TPB) meanstdmax_kernel(
    const float* __restrict__ in, float* __restrict__ out)
{
    int idx = blockIdx.x * TPB + threadIdx.x;   // 0 .. BL*H4-1
    int h4 = idx % H4;
    int bl = idx / H4;

    const float4* p = reinterpret_cast<const float4*>(
        in + (size_t)bl * SEQ * HID + (size_t)h4 * 4);

    float4 s  = make_float4(0.f, 0.f, 0.f, 0.f);
    float4 sq = make_float4(0.f, 0.f, 0.f, 0.f);
    float4 mx = make_float4(-INFINITY, -INFINITY, -INFINITY, -INFINITY);

    #pragma unroll 4
    for (int i = 0; i < SEQ; i++) {
        float4 v = __ldcs(p + (size_t)i * H4);   // streaming, zero reuse
        s.x += v.x;  s.y += v.y;  s.z += v.z;  s.w += v.w;
        sq.x += v.x * v.x;  sq.y += v.y * v.y;
        sq.z += v.z * v.z;  sq.w += v.w * v.w;
        mx.x = fmaxf(mx.x, v.x);  mx.y = fmaxf(mx.y, v.y);
        mx.z = fmaxf(mx.z, v.z);  mx.w = fmaxf(mx.w, v.w);
    }

    const float inv_n  = 1.0f / SEQ;
    const float inv_n1 = 1.0f / (SEQ - 1);
    float4 sd;
    sd.x = sqrtf(fmaxf((sq.x - s.x * (s.x * inv_n)) * inv_n1, 0.0f));
    sd.y = sqrtf(fmaxf((sq.y - s.y * (s.y * inv_n)) * inv_n1, 0.0f));
    sd.z = sqrtf(fmaxf((sq.z - s.z * (s.z * inv_n)) * inv_n1, 0.0f));
    sd.w = sqrtf(fmaxf((sq.w - s.w * (s.w * inv_n)) * inv_n1, 0.0f));

    float4* o = reinterpret_cast<float4*>(out + (size_t)bl * (3 * HID));
    o[h4]            = s;
    o[H4 + h4]       = sd;
    o[2 * H4 + h4]   = mx;
}

extern "C" void kernel_launch(void* const* d_in, const int* in_sizes, int n_in,
                              void* d_out, int out_size)
{
    const float* in = (const float*)d_in[0];
    float* out = (float*)d_out;

    const int total = BL * H4;           // 39936
    const int blocks = total / TPB;      // 624
    meanstdmax_kernel<<<blocks, TPB>>>(in, out);
}

// round 4
// speedup vs baseline: 2.1710x; 2.1710x over previous
#include <cuda_runtime.h>
#include <math.h>

// hidden_states: [16, 13, 512, 768] fp32, reduce over axis=2 (512)
// out: [16, 13, 2304] = concat(sum, std(ddof=1), max) along last axis.
//
// R4: float4 loads AND full parallelism.
// CTA = 256 thr = 8 warps: handles one bl and 64 h4-columns.
//   warp w -> seq chunk w/2 (128 rows), column half w%2 (32 float4).
// Each warp load = 512 B contiguous. 4992 warps total (same as R2).
// 4-way seq partials combined in shared memory.

#define BL     208        // 16 * 13
#define SEQ    512
#define HID    768
#define H4     (HID / 4)  // 192
#define COLS   64         // h4 columns per CTA
#define NCHUNK 4
#define ROWS   (SEQ / NCHUNK)   // 128
#define TPB    256

__global__ void __launch_bounds__(TPB) meanstdmax_kernel(
    const float* __restrict__ in, float* __restrict__ out)
{
    __shared__ float4 sh_s [TPB];
    __shared__ float4 sh_sq[TPB];
    __shared__ float4 sh_mx[TPB];

    const int tid  = threadIdx.x;
    const int warp = tid >> 5;
    const int lane = tid & 31;

    const int bl   = blockIdx.x / 3;
    const int hgrp = blockIdx.x % 3;

    const int col   = ((warp & 1) << 5) + lane;   // 0..63 within CTA
    const int chunk = warp >> 1;                  // 0..3
    const int h4    = hgrp * COLS + col;

    const float4* p = reinterpret_cast<const float4*>(
        in + (size_t)bl * SEQ * HID) + (size_t)chunk * ROWS * H4 + h4;

    float4 s  = make_float4(0.f, 0.f, 0.f, 0.f);
    float4 sq = make_float4(0.f, 0.f, 0.f, 0.f);
    float4 mx = make_float4(-INFINITY, -INFINITY, -INFINITY, -INFINITY);

    #pragma unroll 8
    for (int i = 0; i < ROWS; i++) {
        float4 v = __ldcs(p + (size_t)i * H4);
        s.x += v.x;  s.y += v.y;  s.z += v.z;  s.w += v.w;
        sq.x += v.x * v.x;  sq.y += v.y * v.y;
        sq.z += v.z * v.z;  sq.w += v.w * v.w;
        mx.x = fmaxf(mx.x, v.x);  mx.y = fmaxf(mx.y, v.y);
        mx.z = fmaxf(mx.z, v.z);  mx.w = fmaxf(mx.w, v.w);
    }

    // stash partials: layout [chunk][col]
    sh_s [chunk * COLS + col] = s;
    sh_sq[chunk * COLS + col] = sq;
    sh_mx[chunk * COLS + col] = mx;
    __syncthreads();

    if (tid < COLS) {
        float4 ts  = sh_s [tid];
        float4 tsq = sh_sq[tid];
        float4 tmx = sh_mx[tid];
        #pragma unroll
        for (int c = 1; c < NCHUNK; c++) {
            float4 a = sh_s [c * COLS + tid];
            float4 b = sh_sq[c * COLS + tid];
            float4 m = sh_mx[c * COLS + tid];
            ts.x += a.x;  ts.y += a.y;  ts.z += a.z;  ts.w += a.w;
            tsq.x += b.x; tsq.y += b.y; tsq.z += b.z; tsq.w += b.w;
            tmx.x = fmaxf(tmx.x, m.x); tmx.y = fmaxf(tmx.y, m.y);
            tmx.z = fmaxf(tmx.z, m.z); tmx.w = fmaxf(tmx.w, m.w);
        }

        const float inv_n  = 1.0f / SEQ;
        const float inv_n1 = 1.0f / (SEQ - 1);
        float4 sd;
        sd.x = sqrtf(fmaxf((tsq.x - ts.x * (ts.x * inv_n)) * inv_n1, 0.0f));
        sd.y = sqrtf(fmaxf((tsq.y - ts.y * (ts.y * inv_n)) * inv_n1, 0.0f));
        sd.z = sqrtf(fmaxf((tsq.z - ts.z * (ts.z * inv_n)) * inv_n1, 0.0f));
        sd.w = sqrtf(fmaxf((tsq.w - ts.w * (ts.w * inv_n)) * inv_n1, 0.0f));

        const int oh4 = hgrp * COLS + tid;
        float4* o = reinterpret_cast<float4*>(out + (size_t)bl * (3 * HID));
        o[oh4]            = ts;
        o[H4 + oh4]       = sd;
        o[2 * H4 + oh4]   = tmx;
    }
}

extern "C" void kernel_launch(void* const* d_in, const int* in_sizes, int n_in,
                              void* d_out, int out_size)
{
    const float* in = (const float*)d_in[0];
    float* out = (float*)d_out;

    const int blocks = BL * 3;   // 624
    meanstdmax_kernel<<<blocks, TPB>>>(in, out);
}

// round 5
// speedup vs baseline: 2.3314x; 1.0739x over previous
#include <cuda_runtime.h>
#include <math.h>
#include <stdint.h>

// hidden_states: [16, 13, 512, 768] fp32, reduce over axis=2 (512)
// out: [16, 13, 2304] = concat(sum, std(ddof=1), max).
//
// R5: TMA bulk-copy pipeline. CTA = (bl, 64-row seq chunk), 1664 CTAs.
// cp.async.bulk 12KB/stage (4 rows), 3-stage mbarrier pipeline, 256
// consumer threads reduce from smem. Partials -> scratch -> combine kernel.

#define BL     208
#define SEQ    512
#define HID    768
#define RPC    64              // rows per CTA
#define NQ     (SEQ / RPC)     // 8
#define SROWS  4               // rows per stage
#define NST    3               // pipeline stages
#define NITER  (RPC / SROWS)   // 16
#define TPB    256
#define STAGE_BYTES (SROWS * HID * 4)   // 12288

__device__ float g_scratch[BL * NQ * 3 * HID];   // [bl][q][stat][h], 14.6 MB

__device__ __forceinline__ uint32_t smem_u32(const void* p) {
    uint32_t a;
    asm("{ .reg .u64 t; cvta.to.shared.u64 t, %1; cvt.u32.u64 %0, t; }"
        : "=r"(a) : "l"(p));
    return a;
}

__device__ __forceinline__ void mbar_init(uint32_t bar, uint32_t cnt) {
    asm volatile("mbarrier.init.shared.b64 [%0], %1;" :: "r"(bar), "r"(cnt) : "memory");
}
__device__ __forceinline__ void mbar_arrive(uint32_t bar) {
    asm volatile("mbarrier.arrive.shared.b64 _, [%0];" :: "r"(bar) : "memory");
}
__device__ __forceinline__ void mbar_expect_tx(uint32_t bar, uint32_t tx) {
    asm volatile("mbarrier.arrive.expect_tx.shared.b64 _, [%0], %1;"
                 :: "r"(bar), "r"(tx) : "memory");
}
__device__ __forceinline__ void mbar_wait(uint32_t bar, uint32_t parity) {
    asm volatile(
        "{\n\t"
        ".reg .pred P;\n\t"
        "LAB_WAIT_%=:\n\t"
        "mbarrier.try_wait.parity.acquire.cta.shared::cta.b64 P, [%0], %1, 0x989680;\n\t"
        "@P bra.uni LAB_DONE_%=;\n\t"
        "bra.uni LAB_WAIT_%=;\n\t"
        "LAB_DONE_%=:\n\t"
        "}"
        :: "r"(bar), "r"(parity) : "memory");
}
__device__ __forceinline__ void bulk_ld(uint32_t dst_smem, const void* src,
                                        uint32_t bytes, uint32_t bar) {
    asm volatile(
        "cp.async.bulk.shared::cta.global.mbarrier::complete_tx::bytes "
        "[%0], [%1], %2, [%3];"
        :: "r"(dst_smem), "l"(src), "r"(bytes), "r"(bar) : "memory");
}

__global__ void __launch_bounds__(TPB) partial_kernel(const float* __restrict__ in)
{
    __shared__ __align__(128) float buf[NST][SROWS * HID];   // 36 KB
    __shared__ __align__(8) uint64_t full_bar[NST];
    __shared__ __align__(8) uint64_t empty_bar[NST];

    const int tid = threadIdx.x;
    const int bl  = blockIdx.x / NQ;
    const int q   = blockIdx.x % NQ;

    const float* base = in + (size_t)(bl * SEQ + q * RPC) * HID;

    uint32_t full_a  = smem_u32(&full_bar[0]);
    uint32_t empty_a = smem_u32(&empty_bar[0]);
    uint32_t buf_a[NST];
    #pragma unroll
    for (int s = 0; s < NST; s++) buf_a[s] = smem_u32(&buf[s][0]);

    if (tid == 0) {
        #pragma unroll
        for (int s = 0; s < NST; s++) {
            mbar_init(full_a  + s * 8, 1);
            mbar_init(empty_a + s * 8, TPB);
        }
    }
    __syncthreads();

    // prologue: fill all stages
    if (tid == 0) {
        #pragma unroll
        for (int s = 0; s < NST; s++) {
            mbar_expect_tx(full_a + s * 8, STAGE_BYTES);
            bulk_ld(buf_a[s], base + (size_t)s * SROWS * HID, STAGE_BYTES,
                    full_a + s * 8);
        }
    }

    // per-thread columns: h = tid, tid+256, tid+512
    float s0 = 0.f, s1 = 0.f, s2 = 0.f;
    float q0 = 0.f, q1 = 0.f, q2 = 0.f;
    float m0 = -INFINITY, m1 = -INFINITY, m2 = -INFINITY;

    for (int it = 0; it < NITER; it++) {
        const int st = it % NST;
        const uint32_t par = (uint32_t)(it / NST) & 1u;

        mbar_wait(full_a + st * 8, par);

        const float* b = &buf[st][0];
        #pragma unroll
        for (int r = 0; r < SROWS; r++) {
            float v0 = b[r * HID + tid];
            float v1 = b[r * HID + tid + 256];
            float v2 = b[r * HID + tid + 512];
            s0 += v0; q0 += v0 * v0; m0 = fmaxf(m0, v0);
            s1 += v1; q1 += v1 * v1; m1 = fmaxf(m1, v1);
            s2 += v2; q2 += v2 * v2; m2 = fmaxf(m2, v2);
        }

        mbar_arrive(empty_a + st * 8);

        if (tid == 0 && it + NST < NITER) {
            mbar_wait(empty_a + st * 8, par);
            mbar_expect_tx(full_a + st * 8, STAGE_BYTES);
            bulk_ld(buf_a[st], base + (size_t)(it + NST) * SROWS * HID,
                    STAGE_BYTES, full_a + st * 8);
        }
    }

    // write partials: scratch[bl][q][stat][h]
    float* scr = g_scratch + ((size_t)(bl * NQ + q) * 3) * HID;
    scr[tid]             = s0;  scr[tid + 256]           = s1;  scr[tid + 512]           = s2;
    scr[HID + tid]       = q0;  scr[HID + tid + 256]     = q1;  scr[HID + tid + 512]     = q2;
    scr[2 * HID + tid]   = m0;  scr[2 * HID + tid + 256] = m1;  scr[2 * HID + tid + 512] = m2;
}

__global__ void __launch_bounds__(TPB) combine_kernel(float* __restrict__ out)
{
    const int idx = blockIdx.x * TPB + threadIdx.x;   // 0 .. BL*HID-1
    const int h  = idx % HID;
    const int bl = idx / HID;

    float s = 0.f, sq = 0.f, mx = -INFINITY;
    #pragma unroll
    for (int q = 0; q < NQ; q++) {
        const float* scr = g_scratch + ((size_t)(bl * NQ + q) * 3) * HID;
        s  += scr[h];
        sq += scr[HID + h];
        mx  = fmaxf(mx, scr[2 * HID + h]);
    }

    const float mean = s * (1.0f / SEQ);
    const float var  = (sq - s * mean) * (1.0f / (SEQ - 1));
    const float sd   = sqrtf(fmaxf(var, 0.0f));

    float* o = out + (size_t)bl * (3 * HID);
    o[h]           = s;
    o[HID + h]     = sd;
    o[2 * HID + h] = mx;
}

extern "C" void kernel_launch(void* const* d_in, const int* in_sizes, int n_in,
                              void* d_out, int out_size)
{
    const float* in = (const float*)d_in[0];
    float* out = (float*)d_out;

    partial_kernel<<<BL * NQ, TPB>>>(in);               // 1664 CTAs
    combine_kernel<<<(BL * HID) / TPB, TPB>>>(out);     // 624 CTAs
}

// round 6
// speedup vs baseline: 2.4104x; 1.0339x over previous
#include <cuda_runtime.h>
#include <math.h>
#include <stdint.h>

// hidden_states: [16, 13, 512, 768] fp32, reduce over axis=2 (512)
// out: [16, 13, 2304] = concat(sum, std(ddof=1), max).
//
// R6: TMA bulk pipeline, single-wave grid.
// CTA = (bl, 128-row seq chunk) -> 832 CTAs, 6 CTAs/SM (smem-limited) -> 1 wave.
// 3-stage x 12KB cp.async.bulk pipeline, 256 consumer threads.
// Partials (4 per bl) -> 7.3MB scratch (L2-resident) -> light combine kernel.

#define BL     208
#define SEQ    512
#define HID    768
#define RPC    128             // rows per CTA
#define NQ     (SEQ / RPC)     // 4
#define SROWS  4               // rows per stage
#define NST    3               // pipeline stages
#define NITER  (RPC / SROWS)   // 32
#define TPB    256
#define STAGE_BYTES (SROWS * HID * 4)   // 12288

__device__ float g_scratch[BL * NQ * 3 * HID];   // 7.3 MB

__device__ __forceinline__ uint32_t smem_u32(const void* p) {
    uint32_t a;
    asm("{ .reg .u64 t; cvta.to.shared.u64 t, %1; cvt.u32.u64 %0, t; }"
        : "=r"(a) : "l"(p));
    return a;
}
__device__ __forceinline__ void mbar_init(uint32_t bar, uint32_t cnt) {
    asm volatile("mbarrier.init.shared.b64 [%0], %1;" :: "r"(bar), "r"(cnt) : "memory");
}
__device__ __forceinline__ void mbar_arrive(uint32_t bar) {
    asm volatile("mbarrier.arrive.shared.b64 _, [%0];" :: "r"(bar) : "memory");
}
__device__ __forceinline__ void mbar_expect_tx(uint32_t bar, uint32_t tx) {
    asm volatile("mbarrier.arrive.expect_tx.shared.b64 _, [%0], %1;"
                 :: "r"(bar), "r"(tx) : "memory");
}
__device__ __forceinline__ void mbar_wait(uint32_t bar, uint32_t parity) {
    asm volatile(
        "{\n\t"
        ".reg .pred P;\n\t"
        "LAB_WAIT_%=:\n\t"
        "mbarrier.try_wait.parity.acquire.cta.shared::cta.b64 P, [%0], %1, 0x989680;\n\t"
        "@P bra.uni LAB_DONE_%=;\n\t"
        "bra.uni LAB_WAIT_%=;\n\t"
        "LAB_DONE_%=:\n\t"
        "}"
        :: "r"(bar), "r"(parity) : "memory");
}
__device__ __forceinline__ void bulk_ld(uint32_t dst_smem, const void* src,
                                        uint32_t bytes, uint32_t bar) {
    asm volatile(
        "cp.async.bulk.shared::cta.global.mbarrier::complete_tx::bytes "
        "[%0], [%1], %2, [%3];"
        :: "r"(dst_smem), "l"(src), "r"(bytes), "r"(bar) : "memory");
}

__global__ void __launch_bounds__(TPB) partial_kernel(const float* __restrict__ in)
{
    __shared__ __align__(128) float buf[NST][SROWS * HID];   // 36 KB
    __shared__ __align__(8) uint64_t full_bar[NST];
    __shared__ __align__(8) uint64_t empty_bar[NST];

    const int tid = threadIdx.x;
    const int bl  = blockIdx.x / NQ;
    const int q   = blockIdx.x % NQ;

    const float* base = in + (size_t)(bl * SEQ + q * RPC) * HID;

    uint32_t full_a  = smem_u32(&full_bar[0]);
    uint32_t empty_a = smem_u32(&empty_bar[0]);
    uint32_t buf_a[NST];
    #pragma unroll
    for (int s = 0; s < NST; s++) buf_a[s] = smem_u32(&buf[s][0]);

    if (tid == 0) {
        #pragma unroll
        for (int s = 0; s < NST; s++) {
            mbar_init(full_a  + s * 8, 1);
            mbar_init(empty_a + s * 8, TPB);
        }
    }
    __syncthreads();

    if (tid == 0) {
        #pragma unroll
        for (int s = 0; s < NST; s++) {
            mbar_expect_tx(full_a + s * 8, STAGE_BYTES);
            bulk_ld(buf_a[s], base + (size_t)s * SROWS * HID, STAGE_BYTES,
                    full_a + s * 8);
        }
    }

    float s0 = 0.f, s1 = 0.f, s2 = 0.f;
    float q0 = 0.f, q1 = 0.f, q2 = 0.f;
    float m0 = -INFINITY, m1 = -INFINITY, m2 = -INFINITY;

    for (int it = 0; it < NITER; it++) {
        const int st = it % NST;
        const uint32_t par = (uint32_t)(it / NST) & 1u;

        mbar_wait(full_a + st * 8, par);

        const float* b = &buf[st][0];
        #pragma unroll
        for (int r = 0; r < SROWS; r++) {
            float v0 = b[r * HID + tid];
            float v1 = b[r * HID + tid + 256];
            float v2 = b[r * HID + tid + 512];
            s0 += v0; q0 += v0 * v0; m0 = fmaxf(m0, v0);
            s1 += v1; q1 += v1 * v1; m1 = fmaxf(m1, v1);
            s2 += v2; q2 += v2 * v2; m2 = fmaxf(m2, v2);
        }

        mbar_arrive(empty_a + st * 8);

        if (tid == 0 && it + NST < NITER) {
            mbar_wait(empty_a + st * 8, par);
            mbar_expect_tx(full_a + st * 8, STAGE_BYTES);
            bulk_ld(buf_a[st], base + (size_t)(it + NST) * SROWS * HID,
                    STAGE_BYTES, full_a + st * 8);
        }
    }

    float* scr = g_scratch + ((size_t)(bl * NQ + q) * 3) * HID;
    scr[tid]             = s0;  scr[tid + 256]           = s1;  scr[tid + 512]           = s2;
    scr[HID + tid]       = q0;  scr[HID + tid + 256]     = q1;  scr[HID + tid + 512]     = q2;
    scr[2 * HID + tid]   = m0;  scr[2 * HID + tid + 256] = m1;  scr[2 * HID + tid + 512] = m2;
}

__global__ void __launch_bounds__(TPB) combine_kernel(float* __restrict__ out)
{
    const int idx = blockIdx.x * TPB + threadIdx.x;   // 0 .. BL*HID-1
    const int h  = idx % HID;
    const int bl = idx / HID;

    float s = 0.f, sq = 0.f, mx = -INFINITY;
    #pragma unroll
    for (int q = 0; q < NQ; q++) {
        const float* scr = g_scratch + ((size_t)(bl * NQ + q) * 3) * HID;
        s  += scr[h];
        sq += scr[HID + h];
        mx  = fmaxf(mx, scr[2 * HID + h]);
    }

    const float mean = s * (1.0f / SEQ);
    const float var  = (sq - s * mean) * (1.0f / (SEQ - 1));
    const float sd   = sqrtf(fmaxf(var, 0.0f));

    float* o = out + (size_t)bl * (3 * HID);
    o[h]           = s;
    o[HID + h]     = sd;
    o[2 * HID + h] = mx;
}

extern "C" void kernel_launch(void* const* d_in, const int* in_sizes, int n_in,
                              void* d_out, int out_size)
{
    const float* in = (const float*)d_in[0];
    float* out = (float*)d_out;

    partial_kernel<<<BL * NQ, TPB>>>(in);               // 832 CTAs, one wave
    combine_kernel<<<(BL * HID) / TPB, TPB>>>(out);     // 624 CTAs
}